// round 6
// baseline (speedup 1.0000x reference)
#include <cuda_runtime.h>
#include <cuda_fp16.h>
#include <math.h>

#define NN 100000
#define EE 1600000
#define HH 64

typedef unsigned long long u64;

// ---------------- scratch (device globals) ----------------------------------
__device__ __half g_y[2 * (size_t)NN * HH];  // GEMM outputs [rel][N][64] (fp16)
__device__ __half g_h[2 * (size_t)NN * HH];  // layer-1 activations (fp16)
__device__ float  g_norms[4 * NN];           // csp | cdp | csn | cdn
__device__ int    g_cnt[4 * NN];             // int degree counts (same layout)
__device__ int    g_off[2 * (NN + 1)];       // CSR row offsets (dst) per relation
__device__ int    g_cur[2 * NN];             // scatter cursors
__device__ int    g_csr[2 * EE];             // src ids grouped by dst
__device__ int    g_bsum[2 * 128];           // scan block sums
__device__ float  g_proj[4 * NN];            // classifier projections [N][4]

// ---------------- packed fp32x2 ---------------------------------------------
__device__ __forceinline__ u64 pack2(float a, float b) {
    u64 r; asm("mov.b64 %0, {%1,%2};" : "=l"(r) : "f"(a), "f"(b)); return r;
}
__device__ __forceinline__ float2 unpk2(u64 v) {
    float2 f; asm("mov.b64 {%0,%1}, %2;" : "=f"(f.x), "=f"(f.y) : "l"(v)); return f;
}
__device__ __forceinline__ void fma2(u64& d, u64 a, u64 b) {
    asm("fma.rn.f32x2 %0, %1, %2, %3;" : "=l"(d) : "l"(a), "l"(b), "l"(d));
}

// ---------------- utility ----------------------------------------------------
__global__ void zero_int4(int4* __restrict__ p, int n4) {
    int t = blockIdx.x * blockDim.x + threadIdx.x;
    if (t < n4) p[t] = make_int4(0, 0, 0, 0);
}

__global__ void deg4_kernel(const int* __restrict__ sp, const int* __restrict__ dp,
                            const int* __restrict__ sn, const int* __restrict__ dn,
                            int* __restrict__ cnt, int n, int nE) {
    int t = blockIdx.x * blockDim.x + threadIdx.x;
    if (t >= nE) return;
    int w = blockIdx.y;
    const int* idx = (w == 0) ? sp : (w == 1) ? dp : (w == 2) ? sn : dn;
    atomicAdd(cnt + (size_t)w * n + idx[t], 1);
}

__global__ void norm_kernel(const int* __restrict__ cnt, float* __restrict__ norms, int n4) {
    int t = blockIdx.x * blockDim.x + threadIdx.x;
    if (t < n4) {
        int d = cnt[t];
        norms[t] = (d > 0) ? rsqrtf((float)d) : 0.f;
    }
}

// ---------------- prefix scan of dst counts ----------------------------------
__global__ void scan_partial(const int* __restrict__ cnt, int* __restrict__ bsum, int n) {
    int rel = blockIdx.y;
    const int* c = cnt + (size_t)(1 + 2 * rel) * n;
    int tid = threadIdx.x;
    int base = blockIdx.x * 1024 + tid * 4;
    int s = 0;
    #pragma unroll
    for (int j = 0; j < 4; j++) { int i = base + j; if (i < n) s += c[i]; }
    __shared__ int sm[256];
    sm[tid] = s; __syncthreads();
    for (int o = 128; o > 0; o >>= 1) {
        if (tid < o) sm[tid] += sm[tid + o];
        __syncthreads();
    }
    if (tid == 0) bsum[rel * 128 + blockIdx.x] = sm[0];
}

__global__ void scan_blocksums(int* __restrict__ bsum, int* __restrict__ off,
                               int n, int nb, int nEp, int nEn) {
    int rel = blockIdx.x;
    int tid = threadIdx.x;   // 128 threads
    __shared__ int sm[128];
    int v = (tid < nb) ? bsum[rel * 128 + tid] : 0;
    sm[tid] = v; __syncthreads();
    for (int o = 1; o < 128; o <<= 1) {
        int a = (tid >= o) ? sm[tid - o] : 0;
        __syncthreads();
        sm[tid] += a;
        __syncthreads();
    }
    bsum[rel * 128 + tid] = sm[tid] - v;   // exclusive
    if (tid == 0) off[(size_t)rel * (n + 1) + n] = rel ? nEn : nEp;
}

__global__ void scan_final(const int* __restrict__ cnt, const int* __restrict__ bsum,
                           int* __restrict__ off, int* __restrict__ cur, int n) {
    int rel = blockIdx.y;
    const int* c = cnt + (size_t)(1 + 2 * rel) * n;
    int* o = off + (size_t)rel * (n + 1);
    int* cu = cur + (size_t)rel * n;
    int tid = threadIdx.x;
    int base = blockIdx.x * 1024 + tid * 4;
    int v[4];
    #pragma unroll
    for (int j = 0; j < 4; j++) { int i = base + j; v[j] = (i < n) ? c[i] : 0; }
    int tsum = v[0] + v[1] + v[2] + v[3];
    __shared__ int sm[256];
    sm[tid] = tsum; __syncthreads();
    for (int ofs = 1; ofs < 256; ofs <<= 1) {
        int a = (tid >= ofs) ? sm[tid - ofs] : 0;
        __syncthreads();
        sm[tid] += a;
        __syncthreads();
    }
    int ex = bsum[rel * 128 + blockIdx.x] + sm[tid] - tsum;
    #pragma unroll
    for (int j = 0; j < 4; j++) {
        int i = base + j;
        if (i < n) { o[i] = ex; cu[i] = ex; }
        ex += v[j];
    }
}

// ---------------- shared GEMM body: 128 rows/block, 2 rows/thread ------------
template <typename T>
__device__ __forceinline__ void gemm_body(const T* __restrict__ X,
                                          const float* __restrict__ cs,
                                          const float* __restrict__ W,
                                          __half* __restrict__ Yo, int n, int blk) {
    __shared__ float Ws[4096];      // W row-major [k][col], 16 KB
    __shared__ float Xs[8192];      // transposed: Xs[k*128 + r], 32 KB
    int tid = threadIdx.x;
    int row0 = blk * 128;

    #pragma unroll
    for (int i = tid; i < 1024; i += 256) ((float4*)Ws)[i] = ((const float4*)W)[i];

    if (sizeof(T) == 4) {           // fp32 input
        const float* Xf = (const float*)X;
        for (int i = tid; i < 2048; i += 256) {
            int r = i & 127, kq = i >> 7;
            int gr = row0 + r;
            float4 v = (gr < n) ? ((const float4*)Xf)[(size_t)gr * 16 + kq]
                                : make_float4(0.f, 0.f, 0.f, 0.f);
            Xs[(4 * kq + 0) * 128 + r] = v.x;
            Xs[(4 * kq + 1) * 128 + r] = v.y;
            Xs[(4 * kq + 2) * 128 + r] = v.z;
            Xs[(4 * kq + 3) * 128 + r] = v.w;
        }
    } else {                        // fp16 input
        const __half* Xh = (const __half*)X;
        for (int i = tid; i < 1024; i += 256) {
            int r = i & 127, ko = i >> 7;
            int gr = row0 + r;
            uint4 v = (gr < n) ? __ldg((const uint4*)Xh + (size_t)gr * 8 + ko)
                               : make_uint4(0, 0, 0, 0);
            const __half2* hp = (const __half2*)&v;
            #pragma unroll
            for (int q = 0; q < 4; q++) {
                float2 f = __half22float2(hp[q]);
                Xs[(8 * ko + 2 * q + 0) * 128 + r] = f.x;
                Xs[(8 * ko + 2 * q + 1) * 128 + r] = f.y;
            }
        }
    }
    __syncthreads();

    int w = tid >> 5, lane = tid & 31;
    int r1 = (w >> 2) * 32 + lane;       // 0..63
    int r2 = r1 + 64;                    // 64..127
    int cg = (w & 3) * 16;
    u64 a1[8] = {0, 0, 0, 0, 0, 0, 0, 0};
    u64 a2[8] = {0, 0, 0, 0, 0, 0, 0, 0};

    #pragma unroll
    for (int k = 0; k < 64; k++) {
        float xa = Xs[k * 128 + r1];
        float xb = Xs[k * 128 + r2];
        u64 XA = pack2(xa, xa);
        u64 XB = pack2(xb, xb);
        const float* wr = &Ws[k * 64 + cg];
        ulonglong2 w0 = *(const ulonglong2*)(wr + 0);
        ulonglong2 w1 = *(const ulonglong2*)(wr + 4);
        ulonglong2 w2 = *(const ulonglong2*)(wr + 8);
        ulonglong2 w3 = *(const ulonglong2*)(wr + 12);
        fma2(a1[0], XA, w0.x); fma2(a1[1], XA, w0.y);
        fma2(a1[2], XA, w1.x); fma2(a1[3], XA, w1.y);
        fma2(a1[4], XA, w2.x); fma2(a1[5], XA, w2.y);
        fma2(a1[6], XA, w3.x); fma2(a1[7], XA, w3.y);
        fma2(a2[0], XB, w0.x); fma2(a2[1], XB, w0.y);
        fma2(a2[2], XB, w1.x); fma2(a2[3], XB, w1.y);
        fma2(a2[4], XB, w2.x); fma2(a2[5], XB, w2.y);
        fma2(a2[6], XB, w3.x); fma2(a2[7], XB, w3.y);
    }

    #pragma unroll
    for (int rr = 0; rr < 2; rr++) {
        int gr = row0 + (rr ? r2 : r1);
        if (gr >= n) continue;
        u64* acc = rr ? a2 : a1;
        float c = cs[gr];
        __half2 o[8];
        #pragma unroll
        for (int i = 0; i < 8; i++) {
            float2 f = unpk2(acc[i]);
            o[i] = __floats2half2_rn(f.x * c, f.y * c);
        }
        __half* yo = Yo + (size_t)gr * 64 + cg;
        *(uint4*)(yo + 0) = *(const uint4*)&o[0];
        *(uint4*)(yo + 8) = *(const uint4*)&o[4];
    }
}

// ---------------- fat kernel: layer-1 GEMM (both rels) + CSR scatter ---------
__global__ void __launch_bounds__(256)
gemm1_scatter(const float* __restrict__ x, const float* __restrict__ norms,
              const float* __restrict__ W0, const float* __restrict__ W1,
              __half* __restrict__ Y,
              const int* __restrict__ srcp, const int* __restrict__ dstp,
              const int* __restrict__ srcn, const int* __restrict__ dstn,
              int* __restrict__ cur, int* __restrict__ csr,
              int n, int nEp, int nEn, int gGemm, int gScat) {
    int b = blockIdx.x;
    if (b < 2 * gGemm) {
        int rel = b / gGemm;
        gemm_body<float>(x, norms + 2 * (size_t)rel * n,
                         rel ? W1 : W0, Y + (size_t)rel * n * 64, n, b % gGemm);
    } else {
        int sb = b - 2 * gGemm;
        int rel = sb / gScat;
        int e = (sb % gScat) * 256 + threadIdx.x;
        int nE = rel ? nEn : nEp;
        if (e >= nE) return;
        const int* src = rel ? srcn : srcp;
        const int* dst = rel ? dstn : dstp;
        int d = dst[e];
        int p = atomicAdd(cur + (size_t)rel * n + d, 1);
        csr[(size_t)rel * EE + p] = src[e];
    }
}

// ---------------- layer-2 GEMM (fp16 input) ----------------------------------
__global__ void __launch_bounds__(256)
gemm_l2(const __half* __restrict__ h, const float* __restrict__ norms,
        const float* __restrict__ W0, const float* __restrict__ W1,
        __half* __restrict__ Y, int n) {
    int rel = blockIdx.y;
    gemm_body<__half>(h + (size_t)rel * n * 64, norms + 2 * (size_t)rel * n,
                      rel ? W1 : W0, Y + (size_t)rel * n * 64, n, blockIdx.x);
}

// ---------------- CSR pull, LDG.128 lane-split: 4 edges per load -------------
// warp = 4 groups of 8 lanes; group g handles edges j+g; lane covers 8 cols.
__device__ __forceinline__ void csr_sum8(const int* __restrict__ off,
                                         const int* __restrict__ csr,
                                         const uint4* __restrict__ yrow,  // row s at yrow + s*8
                                         int node, int l8, int g, float* acc) {
    #pragma unroll
    for (int q = 0; q < 8; q++) acc[q] = 0.f;
    int j = off[node], end = off[node + 1];
    for (; j + 4 <= end; j += 4) {
        int s = __ldg(csr + j + g);
        uint4 v = __ldg(yrow + (size_t)s * 8 + l8);
        const __half2* hp = (const __half2*)&v;
        #pragma unroll
        for (int q = 0; q < 4; q++) {
            float2 f = __half22float2(hp[q]);
            acc[2 * q] += f.x; acc[2 * q + 1] += f.y;
        }
    }
    if (j < end) {
        int e = j + g;
        if (e < end) {
            int s = __ldg(csr + e);
            uint4 v = __ldg(yrow + (size_t)s * 8 + l8);
            const __half2* hp = (const __half2*)&v;
            #pragma unroll
            for (int q = 0; q < 4; q++) {
                float2 f = __half22float2(hp[q]);
                acc[2 * q] += f.x; acc[2 * q + 1] += f.y;
            }
        }
    }
    // combine the 4 groups
    #pragma unroll
    for (int q = 0; q < 8; q++) {
        acc[q] += __shfl_xor_sync(0xffffffffu, acc[q], 8);
        acc[q] += __shfl_xor_sync(0xffffffffu, acc[q], 16);
    }
}

// layer 1: h_rel[i,:] = half(relu(c_dst[i] * sum y_rel[src] + b0_rel))
__global__ void agg_l1(const __half* __restrict__ y, const int* __restrict__ off,
                       const int* __restrict__ csr, const float* __restrict__ norms,
                       const float* __restrict__ b0p, const float* __restrict__ b0n,
                       __half* __restrict__ h, int n) {
    int rel = blockIdx.y;
    int node = blockIdx.x * 8 + (threadIdx.x >> 5);
    if (node >= n) return;
    int lane = threadIdx.x & 31, l8 = lane & 7, g = lane >> 3;
    float acc[8];
    csr_sum8(off + (size_t)rel * (n + 1), csr + (size_t)rel * EE,
             (const uint4*)(y + (size_t)rel * n * 64), node, l8, g, acc);
    if (g == 0) {
        float c = norms[(size_t)(1 + 2 * rel) * n + node];
        const float* b = (rel ? b0n : b0p) + 8 * l8;
        float4 bA = __ldg((const float4*)b);
        float4 bB = __ldg((const float4*)(b + 4));
        __half2 o[4];
        o[0] = __floats2half2_rn(fmaxf(c * acc[0] + bA.x, 0.f), fmaxf(c * acc[1] + bA.y, 0.f));
        o[1] = __floats2half2_rn(fmaxf(c * acc[2] + bA.z, 0.f), fmaxf(c * acc[3] + bA.w, 0.f));
        o[2] = __floats2half2_rn(fmaxf(c * acc[4] + bB.x, 0.f), fmaxf(c * acc[5] + bB.y, 0.f));
        o[3] = __floats2half2_rn(fmaxf(c * acc[6] + bB.z, 0.f), fmaxf(c * acc[7] + bB.w, 0.f));
        ((uint4*)(h + (size_t)rel * n * 64 + (size_t)node * 64))[l8] = *(const uint4*)o;
    }
}

// layer 2 fused: z = relu(cdp*sumP + b1p) - relu(cdn*sumN + b1n), + proj
__global__ void agg_l2(const __half* __restrict__ y, const int* __restrict__ off,
                       const int* __restrict__ csr, const float* __restrict__ norms,
                       const float* __restrict__ b1p, const float* __restrict__ b1n,
                       const float* __restrict__ Wc,
                       float* __restrict__ z, float* __restrict__ proj, int n) {
    __shared__ float Wcs[256];
    Wcs[threadIdx.x] = Wc[threadIdx.x];   // blockDim == 256
    __syncthreads();

    int node = blockIdx.x * 8 + (threadIdx.x >> 5);
    if (node >= n) return;
    int lane = threadIdx.x & 31, l8 = lane & 7, g = lane >> 3;

    float aP[8], aN[8];
    csr_sum8(off, csr, (const uint4*)y, node, l8, g, aP);
    csr_sum8(off + (n + 1), csr + (size_t)EE, (const uint4*)(y + (size_t)n * 64),
             node, l8, g, aN);
    float cp = norms[(size_t)n + node];
    float cn = norms[3 * (size_t)n + node];
    const float* bp = b1p + 8 * l8;
    const float* bn = b1n + 8 * l8;
    float4 bpA = __ldg((const float4*)bp), bpB = __ldg((const float4*)(bp + 4));
    float4 bnA = __ldg((const float4*)bn), bnB = __ldg((const float4*)(bn + 4));
    float bpv[8] = {bpA.x, bpA.y, bpA.z, bpA.w, bpB.x, bpB.y, bpB.z, bpB.w};
    float bnv[8] = {bnA.x, bnA.y, bnA.z, bnA.w, bnB.x, bnB.y, bnB.z, bnB.w};

    float r[8];
    #pragma unroll
    for (int q = 0; q < 8; q++)
        r[q] = fmaxf(cp * aP[q] + bpv[q], 0.f) - fmaxf(cn * aN[q] + bnv[q], 0.f);

    if (g == 0) {
        float* zo = z + (size_t)node * 64 + 8 * l8;
        *(float4*)(zo + 0) = make_float4(r[0], r[1], r[2], r[3]);
        *(float4*)(zo + 4) = make_float4(r[4], r[5], r[6], r[7]);
    }

    // proj: lane covers cols 8*l8..8*l8+7; Wc row-major [128][2]
    float s0 = 0.f, s1 = 0.f, d0 = 0.f, d1 = 0.f;
    const float4* wsrc = (const float4*)&Wcs[16 * l8];
    const float4* wdst = (const float4*)&Wcs[128 + 16 * l8];
    #pragma unroll
    for (int q = 0; q < 4; q++) {
        float4 ws = wsrc[q];   // (w0 col a, w1 col a, w0 col a+1, w1 col a+1)
        float4 wd = wdst[q];
        s0 += r[2 * q] * ws.x + r[2 * q + 1] * ws.z;
        s1 += r[2 * q] * ws.y + r[2 * q + 1] * ws.w;
        d0 += r[2 * q] * wd.x + r[2 * q + 1] * wd.z;
        d1 += r[2 * q] * wd.y + r[2 * q + 1] * wd.w;
    }
    #pragma unroll
    for (int o = 1; o < 8; o <<= 1) {     // groups are redundant copies
        s0 += __shfl_xor_sync(0xffffffffu, s0, o);
        s1 += __shfl_xor_sync(0xffffffffu, s1, o);
        d0 += __shfl_xor_sync(0xffffffffu, d0, o);
        d1 += __shfl_xor_sync(0xffffffffu, d1, o);
    }
    if (lane == 0) ((float4*)proj)[node] = make_float4(s0, s1, d0, d1);
}

// ---------------- classifier: 2 x 16B per query ------------------------------
__global__ void cls_kernel(const float* __restrict__ p, const int* __restrict__ ei,
                           const float* __restrict__ bc, float* __restrict__ out, int nQ) {
    int q = blockIdx.x * blockDim.x + threadIdx.x;
    if (q >= nQ) return;
    int s = __ldg(ei + q);
    int d = __ldg(ei + nQ + q);
    float4 ps = ((const float4*)p)[s];
    float4 pd = ((const float4*)p)[d];
    float l0 = ps.x + pd.z + bc[0];
    float l1 = ps.y + pd.w + bc[1];
    float2 o;
    o.x = 1.f / (1.f + __expf(-l0));
    o.y = 1.f / (1.f + __expf(-l1));
    ((float2*)out)[q] = o;
}

// ---------------- launch -------------------------------------------------------
static inline int cdiv(long long a, int b) { return (int)((a + b - 1) / b); }

extern "C" void kernel_launch(void* const* d_in, const int* in_sizes, int n_in,
                              void* d_out, int out_size) {
    const float* x    = (const float*)d_in[0];
    const float* W0p  = (const float*)d_in[1];
    const float* b0p  = (const float*)d_in[2];
    const float* W0n  = (const float*)d_in[3];
    const float* b0n  = (const float*)d_in[4];
    const float* W1p  = (const float*)d_in[5];
    const float* b1p  = (const float*)d_in[6];
    const float* W1n  = (const float*)d_in[7];
    const float* b1n  = (const float*)d_in[8];
    const float* Wc   = (const float*)d_in[9];
    const float* bc   = (const float*)d_in[10];
    const int*   srcp = (const int*)d_in[11];
    const int*   dstp = (const int*)d_in[12];
    const int*   srcn = (const int*)d_in[13];
    const int*   dstn = (const int*)d_in[14];
    const int*   ei   = (const int*)d_in[15];

    const int n   = in_sizes[0] / HH;
    const int nEp = in_sizes[11];
    const int nEn = in_sizes[13];
    const int nQ  = in_sizes[15] / 2;

    __half *y, *h;
    float *norms, *pbuf;
    int *cnt, *off, *cur, *csr, *bsum;
    cudaGetSymbolAddress((void**)&y,     g_y);
    cudaGetSymbolAddress((void**)&h,     g_h);
    cudaGetSymbolAddress((void**)&norms, g_norms);
    cudaGetSymbolAddress((void**)&cnt,   g_cnt);
    cudaGetSymbolAddress((void**)&off,   g_off);
    cudaGetSymbolAddress((void**)&cur,   g_cur);
    cudaGetSymbolAddress((void**)&csr,   g_csr);
    cudaGetSymbolAddress((void**)&bsum,  g_bsum);
    cudaGetSymbolAddress((void**)&pbuf,  g_proj);

    float* z     = (float*)d_out;
    float* probs = (float*)d_out + (size_t)n * HH;

    const int nb    = cdiv(n, 1024);
    const int gGemm = cdiv(n, 128);
    const int gScat = cdiv(nEp > nEn ? nEp : nEn, 256);
    const int gAgg  = cdiv(n, 8);

    // degrees + norms + scan
    zero_int4<<<cdiv(n, 256), 256>>>((int4*)cnt, n);
    deg4_kernel<<<dim3(cdiv(nEp, 256), 4), 256>>>(srcp, dstp, srcn, dstn, cnt, n, nEp);
    norm_kernel<<<cdiv(4 * n, 256), 256>>>(cnt, norms, 4 * n);
    scan_partial<<<dim3(nb, 2), 256>>>(cnt, bsum, n);
    scan_blocksums<<<2, 128>>>(bsum, off, n, nb, nEp, nEn);
    scan_final<<<dim3(nb, 2), 256>>>(cnt, bsum, off, cur, n);

    // layer-1 GEMM (both rels) overlapped with CSR scatter (both rels)
    gemm1_scatter<<<2 * gGemm + 2 * gScat, 256>>>(
        x, norms, W0p, W0n, y, srcp, dstp, srcn, dstn, cur, csr,
        n, nEp, nEn, gGemm, gScat);

    // layer-1 aggregation -> h (fp16)
    agg_l1<<<dim3(gAgg, 2), 256>>>(y, off, csr, norms, b0p, b0n, h, n);

    // layer-2 GEMM (fp16 input)
    gemm_l2<<<dim3(gGemm, 2), 256>>>(h, norms, W1p, W1n, y, n);

    // layer-2 aggregation + combine + classifier projection
    agg_l2<<<gAgg, 256>>>(y, off, csr, norms, b1p, b1n, Wc, z, pbuf, n);

    // classifier
    cls_kernel<<<cdiv(nQ, 256), 256>>>(pbuf, ei, bc, probs, nQ);
}

// round 7
// speedup vs baseline: 1.1247x; 1.1247x over previous
#include <cuda_runtime.h>
#include <cuda_fp16.h>
#include <mma.h>
#include <math.h>

using namespace nvcuda;

#define NN 100000
#define EE 1600000
#define HH 64
#define XS_LD 80   // padded smem stride (halves / floats)

typedef unsigned long long u64;

// ---------------- scratch (device globals) ----------------------------------
__device__ __half g_y[2 * (size_t)NN * HH];  // GEMM outputs [rel][N][64] (fp16)
__device__ __half g_h[2 * (size_t)NN * HH];  // layer-1 activations (fp16)
__device__ float  g_norms[4 * NN];           // csp | cdp | csn | cdn
__device__ int    g_cnt[4 * NN];             // int degree counts (same layout)
__device__ int    g_off[2 * (NN + 1)];       // CSR row offsets (dst) per relation
__device__ int    g_cur[2 * NN];             // scatter cursors
__device__ int    g_csr[2 * EE];             // src ids grouped by dst
__device__ int    g_bsum[2 * 128];           // scan block sums
__device__ float  g_proj[4 * NN];            // classifier projections [N][4]

// ---------------- utility ----------------------------------------------------
__global__ void zero_int4(int4* __restrict__ p, int n4) {
    int t = blockIdx.x * blockDim.x + threadIdx.x;
    if (t < n4) p[t] = make_int4(0, 0, 0, 0);
}

__global__ void deg4_kernel(const int* __restrict__ sp, const int* __restrict__ dp,
                            const int* __restrict__ sn, const int* __restrict__ dn,
                            int* __restrict__ cnt, int n, int nE) {
    int t = blockIdx.x * blockDim.x + threadIdx.x;
    if (t >= nE) return;
    int w = blockIdx.y;
    const int* idx = (w == 0) ? sp : (w == 1) ? dp : (w == 2) ? sn : dn;
    atomicAdd(cnt + (size_t)w * n + idx[t], 1);
}

// fused: norms for all 4 count arrays + scan partial sums for the 2 dst arrays
__global__ void scan_partial_norm(const int* __restrict__ cnt, float* __restrict__ norms,
                                  int* __restrict__ bsum, int n) {
    int w = blockIdx.y;                 // 0..3
    const int* c = cnt + (size_t)w * n;
    float* nm = norms + (size_t)w * n;
    int tid = threadIdx.x;
    int base = blockIdx.x * 1024 + tid * 4;
    int s = 0;
    #pragma unroll
    for (int j = 0; j < 4; j++) {
        int i = base + j;
        if (i < n) {
            int d = c[i];
            nm[i] = (d > 0) ? rsqrtf((float)d) : 0.f;
            s += d;
        }
    }
    if (w == 1 || w == 3) {             // dst arrays feed the CSR scan
        __shared__ int sm[256];
        sm[tid] = s; __syncthreads();
        for (int o = 128; o > 0; o >>= 1) {
            if (tid < o) sm[tid] += sm[tid + o];
            __syncthreads();
        }
        if (tid == 0) bsum[(w >> 1) * 128 + blockIdx.x] = sm[0];
    }
}

__global__ void scan_blocksums(int* __restrict__ bsum, int* __restrict__ off,
                               int n, int nb, int nEp, int nEn) {
    int rel = blockIdx.x;
    int tid = threadIdx.x;   // 128 threads
    __shared__ int sm[128];
    int v = (tid < nb) ? bsum[rel * 128 + tid] : 0;
    sm[tid] = v; __syncthreads();
    for (int o = 1; o < 128; o <<= 1) {
        int a = (tid >= o) ? sm[tid - o] : 0;
        __syncthreads();
        sm[tid] += a;
        __syncthreads();
    }
    bsum[rel * 128 + tid] = sm[tid] - v;   // exclusive
    if (tid == 0) off[(size_t)rel * (n + 1) + n] = rel ? nEn : nEp;
}

__global__ void scan_final(const int* __restrict__ cnt, const int* __restrict__ bsum,
                           int* __restrict__ off, int* __restrict__ cur, int n) {
    int rel = blockIdx.y;
    const int* c = cnt + (size_t)(1 + 2 * rel) * n;
    int* o = off + (size_t)rel * (n + 1);
    int* cu = cur + (size_t)rel * n;
    int tid = threadIdx.x;
    int base = blockIdx.x * 1024 + tid * 4;
    int v[4];
    #pragma unroll
    for (int j = 0; j < 4; j++) { int i = base + j; v[j] = (i < n) ? c[i] : 0; }
    int tsum = v[0] + v[1] + v[2] + v[3];
    __shared__ int sm[256];
    sm[tid] = tsum; __syncthreads();
    for (int ofs = 1; ofs < 256; ofs <<= 1) {
        int a = (tid >= ofs) ? sm[tid - ofs] : 0;
        __syncthreads();
        sm[tid] += a;
        __syncthreads();
    }
    int ex = bsum[rel * 128 + blockIdx.x] + sm[tid] - tsum;
    #pragma unroll
    for (int j = 0; j < 4; j++) {
        int i = base + j;
        if (i < n) { o[i] = ex; cu[i] = ex; }
        ex += v[j];
    }
}

// ---------------- wmma GEMM body: 128 rows x 64 cols, K=64 -------------------
// block = 256 threads (8 warps); warp computes 16 rows x 64 cols.
template <typename T>
__device__ __forceinline__ void gemm_body(const T* __restrict__ X,
                                          const float* __restrict__ cs,
                                          const float* __restrict__ W,
                                          __half* __restrict__ Yo, int n, int blk) {
    __shared__ __half Wh[64 * XS_LD];     // [k][n] fp16
    __shared__ __half Xh[128 * XS_LD];    // [r][k] fp16
    __shared__ float  Os[128 * XS_LD];    // fp32 staging
    int tid = threadIdx.x;
    int row0 = blk * 128;

    // W fp32 -> fp16 smem ([k][n], row stride XS_LD)
    for (int i = tid; i < 2048; i += 256) {         // 2048 half2 = 4096 halves
        int k = i >> 5, j = i & 31;                 // j: half2 index within row
        float2 v = ((const float2*)W)[(size_t)k * 32 + j];
        *(__half2*)&Wh[k * XS_LD + 2 * j] = __floats2half2_rn(v.x, v.y);
    }

    // X -> fp16 smem ([r][k], row stride XS_LD)
    if (sizeof(T) == 4) {        // fp32 input
        const float* Xf = (const float*)X;
        for (int i = tid; i < 2048; i += 256) {
            int r = i >> 4, kq = i & 15;
            int gr = row0 + r;
            float4 v = (gr < n) ? ((const float4*)Xf)[(size_t)gr * 16 + kq]
                                : make_float4(0.f, 0.f, 0.f, 0.f);
            __half2 h0 = __floats2half2_rn(v.x, v.y);
            __half2 h1 = __floats2half2_rn(v.z, v.w);
            *(__half2*)&Xh[r * XS_LD + 4 * kq + 0] = h0;
            *(__half2*)&Xh[r * XS_LD + 4 * kq + 2] = h1;
        }
    } else {                     // fp16 input
        const __half* Xq = (const __half*)X;
        for (int i = tid; i < 2048; i += 256) {
            int r = i >> 4, kq = i & 15;            // 4 halves per chunk
            int gr = row0 + r;
            uint v = (gr < n) ? ((const uint2*)Xq)[(size_t)gr * 16 + kq].x : 0u;
            // load 8B chunks instead: use uint2
            uint2 v2 = (gr < n) ? __ldg((const uint2*)Xq + (size_t)gr * 16 + kq)
                                : make_uint2(0, 0);
            *(uint2*)&Xh[r * XS_LD + 4 * kq] = v2;
            (void)v;
        }
    }
    __syncthreads();

    // MMA: warp w -> rows [w*16, w*16+16)
    int w = tid >> 5;
    wmma::fragment<wmma::accumulator, 16, 16, 16, float> acc[4];
    #pragma unroll
    for (int t = 0; t < 4; t++) wmma::fill_fragment(acc[t], 0.f);

    #pragma unroll
    for (int k = 0; k < 64; k += 16) {
        wmma::fragment<wmma::matrix_a, 16, 16, 16, __half, wmma::row_major> a;
        wmma::load_matrix_sync(a, &Xh[(w * 16) * XS_LD + k], XS_LD);
        #pragma unroll
        for (int t = 0; t < 4; t++) {
            wmma::fragment<wmma::matrix_b, 16, 16, 16, __half, wmma::row_major> b;
            wmma::load_matrix_sync(b, &Wh[k * XS_LD + t * 16], XS_LD);
            wmma::mma_sync(acc[t], a, b, acc[t]);
        }
    }
    #pragma unroll
    for (int t = 0; t < 4; t++)
        wmma::store_matrix_sync(&Os[(w * 16) * XS_LD + t * 16], acc[t], XS_LD,
                                wmma::mem_row_major);
    __syncthreads();

    // epilogue: scale by c, convert to fp16, write
    for (int i = tid; i < 2048; i += 256) {
        int r = i >> 4, q = i & 15;
        int gr = row0 + r;
        if (gr >= n) continue;
        float c = cs[gr];
        float4 v = *(const float4*)&Os[r * XS_LD + 4 * q];
        __half2 o0 = __floats2half2_rn(v.x * c, v.y * c);
        __half2 o1 = __floats2half2_rn(v.z * c, v.w * c);
        __half2 o[2] = {o0, o1};
        *(uint2*)(Yo + (size_t)gr * 64 + 4 * q) = *(const uint2*)o;
    }
}

// ---------------- fat kernel: layer-1 GEMM (both rels) + CSR scatter ---------
__global__ void __launch_bounds__(256)
gemm1_scatter(const float* __restrict__ x, const float* __restrict__ norms,
              const float* __restrict__ W0, const float* __restrict__ W1,
              __half* __restrict__ Y,
              const int* __restrict__ srcp, const int* __restrict__ dstp,
              const int* __restrict__ srcn, const int* __restrict__ dstn,
              int* __restrict__ cur, int* __restrict__ csr,
              int n, int nEp, int nEn, int gGemm, int gScat) {
    int b = blockIdx.x;
    if (b < 2 * gGemm) {
        int rel = b / gGemm;
        gemm_body<float>(x, norms + 2 * (size_t)rel * n,
                         rel ? W1 : W0, Y + (size_t)rel * n * 64, n, b % gGemm);
    } else {
        int sb = b - 2 * gGemm;
        int rel = sb / gScat;
        int e = (sb % gScat) * 256 + threadIdx.x;
        int nE = rel ? nEn : nEp;
        if (e >= nE) return;
        const int* src = rel ? srcn : srcp;
        const int* dst = rel ? dstn : dstp;
        int d = dst[e];
        int p = atomicAdd(cur + (size_t)rel * n + d, 1);
        csr[(size_t)rel * EE + p] = src[e];
    }
}

// ---------------- layer-2 GEMM (fp16 input) ----------------------------------
__global__ void __launch_bounds__(256)
gemm_l2(const __half* __restrict__ h, const float* __restrict__ norms,
        const float* __restrict__ W0, const float* __restrict__ W1,
        __half* __restrict__ Y, int n) {
    int rel = blockIdx.y;
    gemm_body<__half>(h + (size_t)rel * n * 64, norms + 2 * (size_t)rel * n,
                      rel ? W1 : W0, Y + (size_t)rel * n * 64, n, blockIdx.x);
}

// ---------------- CSR pull aggregation (fp16 payload, fp32 accum, MLP=4) -----
__device__ __forceinline__ float2 csr_sum(const int* __restrict__ off,
                                          const int* __restrict__ csr,
                                          const __half2* __restrict__ ylane, int node) {
    int j = off[node], end = off[node + 1];
    float2 a0 = make_float2(0.f, 0.f), a1 = make_float2(0.f, 0.f);
    float2 a2 = make_float2(0.f, 0.f), a3 = make_float2(0.f, 0.f);
    for (; j + 4 <= end; j += 4) {
        int s0 = __ldg(csr + j + 0);
        int s1 = __ldg(csr + j + 1);
        int s2 = __ldg(csr + j + 2);
        int s3 = __ldg(csr + j + 3);
        __half2 h0 = __ldg(ylane + (size_t)s0 * 32);
        __half2 h1 = __ldg(ylane + (size_t)s1 * 32);
        __half2 h2 = __ldg(ylane + (size_t)s2 * 32);
        __half2 h3 = __ldg(ylane + (size_t)s3 * 32);
        float2 v0 = __half22float2(h0); a0.x += v0.x; a0.y += v0.y;
        float2 v1 = __half22float2(h1); a1.x += v1.x; a1.y += v1.y;
        float2 v2 = __half22float2(h2); a2.x += v2.x; a2.y += v2.y;
        float2 v3 = __half22float2(h3); a3.x += v3.x; a3.y += v3.y;
    }
    for (; j < end; j++) {
        int s = __ldg(csr + j);
        float2 v = __half22float2(__ldg(ylane + (size_t)s * 32));
        a0.x += v.x; a0.y += v.y;
    }
    a0.x += a1.x; a0.y += a1.y;
    a2.x += a3.x; a2.y += a3.y;
    a0.x += a2.x; a0.y += a2.y;
    return a0;
}

// layer 1: h_rel[i,:] = half(relu(c_dst[i] * sum y_rel[src] + b0_rel))
__global__ void agg_l1(const __half* __restrict__ y, const int* __restrict__ off,
                       const int* __restrict__ csr, const float* __restrict__ norms,
                       const float* __restrict__ b0p, const float* __restrict__ b0n,
                       __half* __restrict__ h, int n) {
    int rel = blockIdx.y;
    int node = blockIdx.x * 8 + (threadIdx.x >> 5);
    if (node >= n) return;
    int lane = threadIdx.x & 31;
    const __half2* yl = (const __half2*)(y + (size_t)rel * n * 64) + lane;
    float2 a = csr_sum(off + (size_t)rel * (n + 1), csr + (size_t)rel * EE, yl, node);
    float c = norms[(size_t)(1 + 2 * rel) * n + node];
    const float* b = rel ? b0n : b0p;
    float rx = fmaxf(c * a.x + b[2 * lane + 0], 0.f);
    float ry = fmaxf(c * a.y + b[2 * lane + 1], 0.f);
    ((__half2*)(h + (size_t)rel * n * 64 + (size_t)node * 64))[lane] =
        __floats2half2_rn(rx, ry);
}

// layer 2 fused: z = relu(cdp*sumP + b1p) - relu(cdn*sumN + b1n) + proj
__global__ void agg_l2(const __half* __restrict__ y, const int* __restrict__ off,
                       const int* __restrict__ csr, const float* __restrict__ norms,
                       const float* __restrict__ b1p, const float* __restrict__ b1n,
                       const float* __restrict__ Wc,
                       float* __restrict__ z, float* __restrict__ proj, int n) {
    __shared__ float Wcs[256];
    Wcs[threadIdx.x] = Wc[threadIdx.x];   // blockDim == 256
    __syncthreads();

    int node = blockIdx.x * 8 + (threadIdx.x >> 5);
    if (node >= n) return;
    int lane = threadIdx.x & 31;
    const __half2* ylP = (const __half2*)y + lane;
    const __half2* ylN = (const __half2*)(y + (size_t)n * 64) + lane;
    float2 aP = csr_sum(off, csr, ylP, node);
    float2 aN = csr_sum(off + (n + 1), csr + (size_t)EE, ylN, node);
    float cp = norms[(size_t)n + node];
    float cn = norms[3 * (size_t)n + node];
    float2 r;
    r.x = fmaxf(cp * aP.x + b1p[2 * lane + 0], 0.f) - fmaxf(cn * aN.x + b1n[2 * lane + 0], 0.f);
    r.y = fmaxf(cp * aP.y + b1p[2 * lane + 1], 0.f) - fmaxf(cn * aN.y + b1n[2 * lane + 1], 0.f);
    *(float2*)(z + (size_t)node * 64 + lane * 2) = r;

    // classifier projections (Wc is [128][2] row-major, cached in smem)
    int k = 2 * lane;
    float s0 = r.x * Wcs[k * 2 + 0] + r.y * Wcs[(k + 1) * 2 + 0];
    float s1 = r.x * Wcs[k * 2 + 1] + r.y * Wcs[(k + 1) * 2 + 1];
    float d0 = r.x * Wcs[128 + k * 2 + 0] + r.y * Wcs[128 + (k + 1) * 2 + 0];
    float d1 = r.x * Wcs[128 + k * 2 + 1] + r.y * Wcs[128 + (k + 1) * 2 + 1];
    #pragma unroll
    for (int o = 16; o > 0; o >>= 1) {
        s0 += __shfl_xor_sync(0xffffffffu, s0, o);
        s1 += __shfl_xor_sync(0xffffffffu, s1, o);
        d0 += __shfl_xor_sync(0xffffffffu, d0, o);
        d1 += __shfl_xor_sync(0xffffffffu, d1, o);
    }
    if (lane == 0) ((float4*)proj)[node] = make_float4(s0, s1, d0, d1);
}

// ---------------- classifier: 2 x 16B per query ------------------------------
__global__ void cls_kernel(const float* __restrict__ p, const int* __restrict__ ei,
                           const float* __restrict__ bc, float* __restrict__ out, int nQ) {
    int q = blockIdx.x * blockDim.x + threadIdx.x;
    if (q >= nQ) return;
    int s = __ldg(ei + q);
    int d = __ldg(ei + nQ + q);
    float4 ps = ((const float4*)p)[s];
    float4 pd = ((const float4*)p)[d];
    float l0 = ps.x + pd.z + bc[0];
    float l1 = ps.y + pd.w + bc[1];
    float2 o;
    o.x = 1.f / (1.f + __expf(-l0));
    o.y = 1.f / (1.f + __expf(-l1));
    ((float2*)out)[q] = o;
}

// ---------------- launch -------------------------------------------------------
static inline int cdiv(long long a, int b) { return (int)((a + b - 1) / b); }

extern "C" void kernel_launch(void* const* d_in, const int* in_sizes, int n_in,
                              void* d_out, int out_size) {
    const float* x    = (const float*)d_in[0];
    const float* W0p  = (const float*)d_in[1];
    const float* b0p  = (const float*)d_in[2];
    const float* W0n  = (const float*)d_in[3];
    const float* b0n  = (const float*)d_in[4];
    const float* W1p  = (const float*)d_in[5];
    const float* b1p  = (const float*)d_in[6];
    const float* W1n  = (const float*)d_in[7];
    const float* b1n  = (const float*)d_in[8];
    const float* Wc   = (const float*)d_in[9];
    const float* bc   = (const float*)d_in[10];
    const int*   srcp = (const int*)d_in[11];
    const int*   dstp = (const int*)d_in[12];
    const int*   srcn = (const int*)d_in[13];
    const int*   dstn = (const int*)d_in[14];
    const int*   ei   = (const int*)d_in[15];

    const int n   = in_sizes[0] / HH;
    const int nEp = in_sizes[11];
    const int nEn = in_sizes[13];
    const int nQ  = in_sizes[15] / 2;

    __half *y, *h;
    float *norms, *pbuf;
    int *cnt, *off, *cur, *csr, *bsum;
    cudaGetSymbolAddress((void**)&y,     g_y);
    cudaGetSymbolAddress((void**)&h,     g_h);
    cudaGetSymbolAddress((void**)&norms, g_norms);
    cudaGetSymbolAddress((void**)&cnt,   g_cnt);
    cudaGetSymbolAddress((void**)&off,   g_off);
    cudaGetSymbolAddress((void**)&cur,   g_cur);
    cudaGetSymbolAddress((void**)&csr,   g_csr);
    cudaGetSymbolAddress((void**)&bsum,  g_bsum);
    cudaGetSymbolAddress((void**)&pbuf,  g_proj);

    float* z     = (float*)d_out;
    float* probs = (float*)d_out + (size_t)n * HH;

    const int nb    = cdiv(n, 1024);
    const int gGemm = cdiv(n, 128);
    const int gScat = cdiv(nEp > nEn ? nEp : nEn, 256);
    const int gAgg  = cdiv(n, 8);

    // degrees + norms + scan
    zero_int4<<<cdiv(n, 256), 256>>>((int4*)cnt, n);
    deg4_kernel<<<dim3(cdiv(nEp, 256), 4), 256>>>(srcp, dstp, srcn, dstn, cnt, n, nEp);
    scan_partial_norm<<<dim3(nb, 4), 256>>>(cnt, norms, bsum, n);
    scan_blocksums<<<2, 128>>>(bsum, off, n, nb, nEp, nEn);
    scan_final<<<dim3(nb, 2), 256>>>(cnt, bsum, off, cur, n);

    // layer-1 GEMM (both rels, tensor cores) overlapped with CSR scatter
    gemm1_scatter<<<2 * gGemm + 2 * gScat, 256>>>(
        x, norms, W0p, W0n, y, srcp, dstp, srcn, dstn, cur, csr,
        n, nEp, nEn, gGemm, gScat);

    // layer-1 aggregation -> h (fp16)
    agg_l1<<<dim3(gAgg, 2), 256>>>(y, off, csr, norms, b0p, b0n, h, n);

    // layer-2 GEMM (fp16 input, tensor cores)
    gemm_l2<<<dim3(gGemm, 2), 256>>>(h, norms, W1p, W1n, y, n);

    // layer-2 aggregation + combine + classifier projection
    agg_l2<<<gAgg, 256>>>(y, off, csr, norms, b1p, b1n, Wc, z, pbuf, n);

    // classifier
    cls_kernel<<<cdiv(nQ, 256), 256>>>(pbuf, ei, bc, probs, nQ);
}